// round 16
// baseline (speedup 1.0000x reference)
#include <cuda_runtime.h>
#include <math.h>

#define Bq    4
#define Sq    1024
#define Cdim  256
#define INNERq 512
#define NHq   8
#define DHq   64

// ---------------- scratch (static __device__, no allocation) ----------------
__device__ float g_xm[Bq*Sq*INNERq];
__device__ float g_z [Bq*Sq*INNERq];
__device__ float g_xa[Bq*Sq*INNERq];
__device__ float g_q [Bq*Sq*INNERq];
__device__ float g_k [Bq*Sq*INNERq];
__device__ float g_v [Bq*Sq*INNERq];
__device__ float g_ig[Bq*NHq*Sq];
__device__ float g_fg[Bq*NHq*Sq];
__device__ float g_lc[Bq*NHq*Sq];
__device__ float g_h [Bq*Sq*INNERq];

// ---------------- up GEMM: 128x128, 8x8 micro, k-tile 32, DOUBLE-BUFFERED ----------------
#define UP_AST 136
#define UP_SMEM_FLOATS (4*32*UP_AST)     // 2 bufs x (A + B) x 32 x 136
#define UP_SMEM_BYTES  (UP_SMEM_FLOATS*4)
__global__ __launch_bounds__(256) void gemm_up(
    const float* __restrict__ A, const float* __restrict__ Bm)
{
    extern __shared__ float gsm[];
    float* As = gsm;                      // [2][32][136]
    float* Bs = gsm + 2*32*UP_AST;        // [2][32][136]
    int tid = threadIdx.x;
    int m0 = blockIdx.y * 128, n0 = blockIdx.x * 128;
    int ty = tid >> 4, tx = tid & 15;
    int lr = tid >> 1, lc16 = (tid & 1) << 4;    // row 0..127, k-off 0|16
    float acc[8][8] = {};
    const float* Ap = A  + (size_t)(m0 + lr) * Cdim + lc16;
    const float* Bp = Bm + (size_t)(n0 + lr) * Cdim + lc16;

    float4 pa[4], pb[4];
    #pragma unroll
    for (int i = 0; i < 4; i++) {
        pa[i] = *(const float4*)(Ap + 4*i);
        pb[i] = *(const float4*)(Bp + 4*i);
    }
    #pragma unroll
    for (int i = 0; i < 4; i++) {
        float* da = &As[(lc16 + 4*i)*UP_AST + lr];
        float* db = &Bs[(lc16 + 4*i)*UP_AST + lr];
        da[0*UP_AST] = pa[i].x; da[1*UP_AST] = pa[i].y; da[2*UP_AST] = pa[i].z; da[3*UP_AST] = pa[i].w;
        db[0*UP_AST] = pb[i].x; db[1*UP_AST] = pb[i].y; db[2*UP_AST] = pb[i].z; db[3*UP_AST] = pb[i].w;
    }
    __syncthreads();

    const int T = Cdim / 32;   // 8
    for (int tb = 0; tb < T; tb++) {
        if (tb + 1 < T) {
            int k0 = (tb + 1) * 32;
            #pragma unroll
            for (int i = 0; i < 4; i++) {
                pa[i] = *(const float4*)(Ap + k0 + 4*i);
                pb[i] = *(const float4*)(Bp + k0 + 4*i);
            }
        }
        const float* Ab = As + (tb & 1)*32*UP_AST;
        const float* Bb = Bs + (tb & 1)*32*UP_AST;
        #pragma unroll 8
        for (int kk = 0; kk < 32; kk++) {
            float4 x0 = *(const float4*)&Ab[kk*UP_AST + 8*ty];
            float4 x1 = *(const float4*)&Ab[kk*UP_AST + 8*ty + 4];
            float4 y0 = *(const float4*)&Bb[kk*UP_AST + 8*tx];
            float4 y1 = *(const float4*)&Bb[kk*UP_AST + 8*tx + 4];
            float av[8] = {x0.x,x0.y,x0.z,x0.w,x1.x,x1.y,x1.z,x1.w};
            float bv[8] = {y0.x,y0.y,y0.z,y0.w,y1.x,y1.y,y1.z,y1.w};
            #pragma unroll
            for (int i = 0; i < 8; i++)
                #pragma unroll
                for (int j = 0; j < 8; j++) acc[i][j] += av[i] * bv[j];
        }
        if (tb + 1 < T) {
            __syncthreads();
            float* Aw = As + ((tb + 1) & 1)*32*UP_AST;
            float* Bw = Bs + ((tb + 1) & 1)*32*UP_AST;
            #pragma unroll
            for (int i = 0; i < 4; i++) {
                float* da = &Aw[(lc16 + 4*i)*UP_AST + lr];
                float* db = &Bw[(lc16 + 4*i)*UP_AST + lr];
                da[0*UP_AST] = pa[i].x; da[1*UP_AST] = pa[i].y; da[2*UP_AST] = pa[i].z; da[3*UP_AST] = pa[i].w;
                db[0*UP_AST] = pb[i].x; db[1*UP_AST] = pb[i].y; db[2*UP_AST] = pb[i].z; db[3*UP_AST] = pb[i].w;
            }
            __syncthreads();
        }
    }

    float* dst; int nn0;
    if (n0 < INNERq) { dst = g_xm; nn0 = n0; } else { dst = g_z; nn0 = n0 - INNERq; }
    #pragma unroll
    for (int i = 0; i < 8; i++) {
        size_t base = (size_t)(m0 + 8*ty + i) * INNERq + nn0 + 8*tx;
        *(float4*)&dst[base]     = make_float4(acc[i][0], acc[i][1], acc[i][2], acc[i][3]);
        *(float4*)&dst[base + 4] = make_float4(acc[i][4], acc[i][5], acc[i][6], acc[i][7]);
    }
}

// ---------------- down GEMM: 128x64, 8x4 micro, k-tile 32, DOUBLE-BUFFERED ----------------
#define DN_BST 68
#define DN_SMEM_FLOATS (2*32*UP_AST + 2*32*DN_BST)
#define DN_SMEM_BYTES  (DN_SMEM_FLOATS*4)
__global__ __launch_bounds__(256) void gemm_down(
    const float* __restrict__ Bm, float* __restrict__ outext)
{
    extern __shared__ float gsm[];
    float* As = gsm;                      // [2][32][136] (128 m rows)
    float* Bs = gsm + 2*32*UP_AST;        // [2][32][68]  (64 n rows)
    int tid = threadIdx.x;
    int m0 = blockIdx.y * 128, n0 = blockIdx.x * 64;
    int ty = tid >> 4, tx = tid & 15;
    int lra = tid >> 1,  lc16 = (tid & 1) << 4;   // A: 128 rows x (0|16)
    int lrb = tid >> 2,  lc8  = (tid & 3) << 3;   // B: 64 rows x (0|8|16|24)
    float acc[8][4] = {};
    const float* Ap = g_h + (size_t)(m0 + lra) * INNERq + lc16;
    const float* Bp = Bm  + (size_t)(n0 + lrb) * INNERq + lc8;

    float4 pa[4], pb[2];
    #pragma unroll
    for (int i = 0; i < 4; i++) pa[i] = *(const float4*)(Ap + 4*i);
    #pragma unroll
    for (int i = 0; i < 2; i++) pb[i] = *(const float4*)(Bp + 4*i);
    #pragma unroll
    for (int i = 0; i < 4; i++) {
        float* da = &As[(lc16 + 4*i)*UP_AST + lra];
        da[0*UP_AST] = pa[i].x; da[1*UP_AST] = pa[i].y; da[2*UP_AST] = pa[i].z; da[3*UP_AST] = pa[i].w;
    }
    #pragma unroll
    for (int i = 0; i < 2; i++) {
        float* db = &Bs[(lc8 + 4*i)*DN_BST + lrb];
        db[0*DN_BST] = pb[i].x; db[1*DN_BST] = pb[i].y; db[2*DN_BST] = pb[i].z; db[3*DN_BST] = pb[i].w;
    }
    __syncthreads();

    const int T = INNERq / 32;   // 16
    for (int tb = 0; tb < T; tb++) {
        if (tb + 1 < T) {
            int k0 = (tb + 1) * 32;
            #pragma unroll
            for (int i = 0; i < 4; i++) pa[i] = *(const float4*)(Ap + k0 + 4*i);
            #pragma unroll
            for (int i = 0; i < 2; i++) pb[i] = *(const float4*)(Bp + k0 + 4*i);
        }
        const float* Ab = As + (tb & 1)*32*UP_AST;
        const float* Bb = Bs + (tb & 1)*32*DN_BST;
        #pragma unroll 8
        for (int kk = 0; kk < 32; kk++) {
            float4 x0 = *(const float4*)&Ab[kk*UP_AST + 8*ty];
            float4 x1 = *(const float4*)&Ab[kk*UP_AST + 8*ty + 4];
            float4 y0 = *(const float4*)&Bb[kk*DN_BST + 4*tx];
            float av[8] = {x0.x,x0.y,x0.z,x0.w,x1.x,x1.y,x1.z,x1.w};
            #pragma unroll
            for (int i = 0; i < 8; i++) {
                acc[i][0] += av[i]*y0.x; acc[i][1] += av[i]*y0.y;
                acc[i][2] += av[i]*y0.z; acc[i][3] += av[i]*y0.w;
            }
        }
        if (tb + 1 < T) {
            __syncthreads();
            float* Aw = As + ((tb + 1) & 1)*32*UP_AST;
            float* Bw = Bs + ((tb + 1) & 1)*32*DN_BST;
            #pragma unroll
            for (int i = 0; i < 4; i++) {
                float* da = &Aw[(lc16 + 4*i)*UP_AST + lra];
                da[0*UP_AST] = pa[i].x; da[1*UP_AST] = pa[i].y; da[2*UP_AST] = pa[i].z; da[3*UP_AST] = pa[i].w;
            }
            #pragma unroll
            for (int i = 0; i < 2; i++) {
                float* db = &Bw[(lc8 + 4*i)*DN_BST + lrb];
                db[0*DN_BST] = pb[i].x; db[1*DN_BST] = pb[i].y; db[2*DN_BST] = pb[i].z; db[3*DN_BST] = pb[i].w;
            }
            __syncthreads();
        }
    }
    #pragma unroll
    for (int i = 0; i < 8; i++) {
        size_t base = (size_t)(m0 + 8*ty + i) * Cdim + n0 + 4*tx;
        *(float4*)&outext[base] = make_float4(acc[i][0], acc[i][1], acc[i][2], acc[i][3]);
    }
}

// ---------------- fused conv + silu + per-block qkv + gate dots ----------------
__global__ __launch_bounds__(128) void fused_conv_qkv_gates(
    const float* __restrict__ conv_w, const float* __restrict__ conv_b,
    const float* __restrict__ Wq, const float* __restrict__ Wk, const float* __restrict__ Wv,
    const float* __restrict__ W_i, const float* __restrict__ b_i,
    const float* __restrict__ W_f, const float* __restrict__ b_f)
{
    __shared__ float sh[3 * INNERq];
    int bs = blockIdx.x;
    int b = bs >> 10;
    int s = bs & 1023;
    int t = threadIdx.x;
    size_t rowbase = (size_t)bs * INNERq;

    float xm4[4], xa4[4];
    #pragma unroll
    for (int j = 0; j < 4; j++) {
        int c = t*4 + j;
        float a = conv_b[c];
        #pragma unroll
        for (int kk = 0; kk < 4; kk++) {
            int sp = s - 3 + kk;
            if (sp >= 0) a += g_xm[((size_t)(b*Sq + sp)) * INNERq + c] * conv_w[c*4 + kk];
        }
        float sg = 1.f / (1.f + __expf(-a));
        xa4[j] = a * sg;
        g_xa[rowbase + c] = xa4[j];
        xm4[j] = g_xm[rowbase + c];
    }

    float q4[4], k4[4], v4[4];
    #pragma unroll
    for (int o = 0; o < 4; o++) {
        float aq = 0.f, ak = 0.f, av = 0.f;
        #pragma unroll
        for (int d = 0; d < 4; d++) {
            aq += Wq[t*16 + o*4 + d] * xa4[d];
            ak += Wk[t*16 + o*4 + d] * xa4[d];
            av += Wv[t*16 + o*4 + d] * xm4[d];
        }
        q4[o] = aq; k4[o] = ak; v4[o] = av;
        sh[t*4 + o]            = aq;
        sh[INNERq + t*4 + o]   = ak;
        sh[2*INNERq + t*4 + o] = av;
    }
    *(float4*)&g_q[rowbase + t*4] = make_float4(q4[0], q4[1], q4[2], q4[3]);
    *(float4*)&g_k[rowbase + t*4] = make_float4(k4[0], k4[1], k4[2], k4[3]);
    *(float4*)&g_v[rowbase + t*4] = make_float4(v4[0], v4[1], v4[2], v4[3]);
    __syncthreads();

    int w = t >> 5, l = t & 31;
    #pragma unroll
    for (int g4 = 0; g4 < 4; g4++) {
        int g = w*4 + g4;
        int h = g & 7;
        const float* Wt = (g < 8 ? W_i : W_f) + h * 1536;
        float acc = 0.f;
        for (int idx = l*4; idx < 1536; idx += 128) {
            float4 sv = *(const float4*)&sh[idx];
            float4 wv = *(const float4*)&Wt[idx];
            acc += sv.x*wv.x + sv.y*wv.y + sv.z*wv.z + sv.w*wv.w;
        }
        #pragma unroll
        for (int o = 16; o; o >>= 1) acc += __shfl_xor_sync(0xffffffffu, acc, o);
        if (l == 0) {
            if (g < 8) g_ig[(size_t)(b*NHq + h) * Sq + s] = acc + b_i[h];
            else       g_fg[(size_t)(b*NHq + h) * Sq + s] = acc + b_f[h];
        }
    }
}

// ---------------- log-sigmoid + inclusive cumsum over S per (b,h) ----------------
__global__ __launch_bounds__(1024) void scan_kernel()
{
    int bh = blockIdx.x;
    int s = threadIdx.x;
    float x = g_fg[(size_t)bh * Sq + s];
    float lf = fminf(x, 0.f) - log1pf(expf(-fabsf(x)));
    __shared__ float sc[Sq];
    sc[s] = lf;
    __syncthreads();
    for (int off = 1; off < Sq; off <<= 1) {
        float tv = (s >= off) ? sc[s - off] : 0.f;
        __syncthreads();
        sc[s] += tv;
        __syncthreads();
    }
    g_lc[(size_t)bh * Sq + s] = sc[s];
}

// ---------------- attn v6 (R14, unchanged): 32-row tiles, 1024 blocks, 128 threads ----------------
#define AST   68
#define QST   36
#define ATT_SMEM_FLOATS (64*QST + 2*64*AST + 32*AST + 2*64 + 5*32)
#define ATT_SMEM_BYTES  (ATT_SMEM_FLOATS*4)

__global__ __launch_bounds__(128) void attn_kernel(
    const float* __restrict__ norm_w, const float* __restrict__ skipw)
{
    extern __shared__ float sm[];
    float* Qt = sm;
    float* Kt = Qt + 64*QST;
    float* Vs = Kt + 64*AST;
    float* Pt = Vs + 64*AST;
    float* pm       = Pt + 32*AST;
    float* ej       = pm + 64;
    float* m_row    = ej + 64;
    float* sc_row   = m_row + 32;
    float* Ei_row   = sc_row + 32;
    float* ssum_row = Ei_row + 32;
    float* lci_row  = ssum_row + 32;

    int xblk = blockIdx.x;
    int r32 = 31 - (xblk >> 5);
    int bh = xblk & 31;
    int b = bh >> 3, h = bh & 7;
    int i0 = r32 * 32;
    int t = threadIdx.x;
    int tx = t & 15, ty = t >> 4;

    #pragma unroll
    for (int e4 = 0; e4 < 4; e4++) {
        int e = t + 128 * e4;
        int row = e >> 4, c4 = (e & 15) << 2;
        float4 qv = *(const float4*)&g_q[((size_t)(b*Sq + i0 + row)) * INNERq + h*DHq + c4];
        Qt[(c4+0)*QST + row] = qv.x;
        Qt[(c4+1)*QST + row] = qv.y;
        Qt[(c4+2)*QST + row] = qv.z;
        Qt[(c4+3)*QST + row] = qv.w;
    }
    if (t < 32) {
        lci_row[t]  = g_lc[(size_t)bh*Sq + i0 + t];
        m_row[t]    = -3.4e38f;
        ssum_row[t] = 0.f;
    }

    float acc[4][4];
    #pragma unroll
    for (int a = 0; a < 4; a++)
        #pragma unroll
        for (int d = 0; d < 4; d++) acc[a][d] = 0.f;

    int ntiles = (r32 >> 1) + 1;
    for (int jt = 0; jt < ntiles; jt++) {
        int j0 = jt * 64;
        __syncthreads();

        #pragma unroll
        for (int e4 = 0; e4 < 8; e4++) {
            int e = t + 128*e4;
            int row = e >> 4, c4 = (e & 15) << 2;
            size_t gb = ((size_t)(b*Sq + j0 + row)) * INNERq + h*DHq + c4;
            float4 kv = *(const float4*)&g_k[gb];
            float4 vv = *(const float4*)&g_v[gb];
            Kt[(c4+0)*AST + row] = kv.x*0.125f;
            Kt[(c4+1)*AST + row] = kv.y*0.125f;
            Kt[(c4+2)*AST + row] = kv.z*0.125f;
            Kt[(c4+3)*AST + row] = kv.w*0.125f;
            *(float4*)&Vs[row*AST + c4] = vv;
        }
        if (t < 32) {
            int l = t;
            size_t gbase = (size_t)bh*Sq + j0;
            float a0 = g_ig[gbase + l]      - g_lc[gbase + l];
            float a1 = g_ig[gbase + 32 + l] - g_lc[gbase + 32 + l];
            float p0 = a0;
            #pragma unroll
            for (int off = 1; off < 32; off <<= 1) {
                float u = __shfl_up_sync(0xffffffffu, p0, off);
                if (l >= off) p0 = fmaxf(p0, u);
            }
            float max0 = __shfl_sync(0xffffffffu, p0, 31);
            float p1 = a1;
            #pragma unroll
            for (int off = 1; off < 32; off <<= 1) {
                float u = __shfl_up_sync(0xffffffffu, p1, off);
                if (l >= off) p1 = fmaxf(p1, u);
            }
            p1 = fmaxf(p1, max0);
            float pmAll = __shfl_sync(0xffffffffu, p1, 31);
            pm[l]      = p0;
            pm[32 + l] = p1;
            ej[l]      = __expf(a0 - pmAll);
            ej[32 + l] = __expf(a1 - pmAll);
            __syncwarp();
            int r = l;
            int jm = i0 + r - j0 + 1;
            jm = jm > 64 ? 64 : jm;
            float mo = m_row[r];
            float rowmax = lci_row[r] + pm[jm-1];
            float mnew = fmaxf(mo, rowmax);
            float sc = __expf(mo - mnew);
            sc_row[r] = sc;
            Ei_row[r] = __expf(lci_row[r] + pmAll - mnew);
            m_row[r]  = mnew;
            ssum_row[r] *= sc;
        }
        __syncthreads();

        #pragma unroll
        for (int a = 0; a < 4; a++) {
            float sc = sc_row[4*ty + a];
            #pragma unroll
            for (int d = 0; d < 4; d++) acc[a][d] *= sc;
        }

        float s[4][4];
        #pragma unroll
        for (int a = 0; a < 4; a++)
            #pragma unroll
            for (int c = 0; c < 4; c++) s[a][c] = 0.f;
        #pragma unroll 8
        for (int kk = 0; kk < 64; kk++) {
            float4 aq = *(const float4*)&Qt[kk*QST + 4*ty];
            float4 bk = *(const float4*)&Kt[kk*AST + 4*tx];
            s[0][0] += aq.x*bk.x; s[0][1] += aq.x*bk.y; s[0][2] += aq.x*bk.z; s[0][3] += aq.x*bk.w;
            s[1][0] += aq.y*bk.x; s[1][1] += aq.y*bk.y; s[1][2] += aq.y*bk.z; s[1][3] += aq.y*bk.w;
            s[2][0] += aq.z*bk.x; s[2][1] += aq.z*bk.y; s[2][2] += aq.z*bk.z; s[2][3] += aq.z*bk.w;
            s[3][0] += aq.w*bk.x; s[3][1] += aq.w*bk.y; s[3][2] += aq.w*bk.z; s[3][3] += aq.w*bk.w;
        }
        {
            float e0 = ej[4*tx], e1 = ej[4*tx+1], e2 = ej[4*tx+2], e3 = ej[4*tx+3];
            bool diag = (jt == ntiles - 1);
            int jg = j0 + 4*tx;
            #pragma unroll
            for (int a = 0; a < 4; a++) {
                int rr = 4*ty + a;
                float Ei = Ei_row[rr];
                float p0 = s[a][0]*Ei*e0;
                float p1 = s[a][1]*Ei*e1;
                float p2 = s[a][2]*Ei*e2;
                float p3 = s[a][3]*Ei*e3;
                if (diag) {
                    int ig = i0 + rr;
                    if (jg     > ig) p0 = 0.f;
                    if (jg + 1 > ig) p1 = 0.f;
                    if (jg + 2 > ig) p2 = 0.f;
                    if (jg + 3 > ig) p3 = 0.f;
                }
                *(float4*)&Pt[rr*AST + 4*tx] = make_float4(p0, p1, p2, p3);
                float part = (p0 + p1) + (p2 + p3);
                part += __shfl_xor_sync(0xffffffffu, part, 1);
                part += __shfl_xor_sync(0xffffffffu, part, 2);
                part += __shfl_xor_sync(0xffffffffu, part, 4);
                part += __shfl_xor_sync(0xffffffffu, part, 8);
                if (tx == 0) ssum_row[rr] += part;
            }
        }
        __syncthreads();

        #pragma unroll 4
        for (int jj = 0; jj < 64; jj += 4) {
            float4 pa0 = *(const float4*)&Pt[(4*ty+0)*AST + jj];
            float4 pa1 = *(const float4*)&Pt[(4*ty+1)*AST + jj];
            float4 pa2 = *(const float4*)&Pt[(4*ty+2)*AST + jj];
            float4 pa3 = *(const float4*)&Pt[(4*ty+3)*AST + jj];
            float4 vb0 = *(const float4*)&Vs[(jj+0)*AST + 4*tx];
            float4 vb1 = *(const float4*)&Vs[(jj+1)*AST + 4*tx];
            float4 vb2 = *(const float4*)&Vs[(jj+2)*AST + 4*tx];
            float4 vb3 = *(const float4*)&Vs[(jj+3)*AST + 4*tx];
            acc[0][0] += pa0.x*vb0.x + pa0.y*vb1.x + pa0.z*vb2.x + pa0.w*vb3.x;
            acc[0][1] += pa0.x*vb0.y + pa0.y*vb1.y + pa0.z*vb2.y + pa0.w*vb3.y;
            acc[0][2] += pa0.x*vb0.z + pa0.y*vb1.z + pa0.z*vb2.z + pa0.w*vb3.z;
            acc[0][3] += pa0.x*vb0.w + pa0.y*vb1.w + pa0.z*vb2.w + pa0.w*vb3.w;
            acc[1][0] += pa1.x*vb0.x + pa1.y*vb1.x + pa1.z*vb2.x + pa1.w*vb3.x;
            acc[1][1] += pa1.x*vb0.y + pa1.y*vb1.y + pa1.z*vb2.y + pa1.w*vb3.y;
            acc[1][2] += pa1.x*vb0.z + pa1.y*vb1.z + pa1.z*vb2.z + pa1.w*vb3.z;
            acc[1][3] += pa1.x*vb0.w + pa1.y*vb1.w + pa1.z*vb2.w + pa1.w*vb3.w;
            acc[2][0] += pa2.x*vb0.x + pa2.y*vb1.x + pa2.z*vb2.x + pa2.w*vb3.x;
            acc[2][1] += pa2.x*vb0.y + pa2.y*vb1.y + pa2.z*vb2.y + pa2.w*vb3.y;
            acc[2][2] += pa2.x*vb0.z + pa2.y*vb1.z + pa2.z*vb2.z + pa2.w*vb3.z;
            acc[2][3] += pa2.x*vb0.w + pa2.y*vb1.w + pa2.z*vb2.w + pa2.w*vb3.w;
            acc[3][0] += pa3.x*vb0.x + pa3.y*vb1.x + pa3.z*vb2.x + pa3.w*vb3.x;
            acc[3][1] += pa3.x*vb0.y + pa3.y*vb1.y + pa3.z*vb2.y + pa3.w*vb3.y;
            acc[3][2] += pa3.x*vb0.z + pa3.y*vb1.z + pa3.z*vb2.z + pa3.w*vb3.z;
            acc[3][3] += pa3.x*vb0.w + pa3.y*vb1.w + pa3.z*vb2.w + pa3.w*vb3.w;
        }
    }

    __syncthreads();
    #pragma unroll
    for (int a = 0; a < 4; a++)
        *(float4*)&Vs[(4*ty + a)*AST + 4*tx] =
            make_float4(acc[a][0], acc[a][1], acc[a][2], acc[a][3]);
    __syncthreads();

    {
        int row = t >> 2, qd = t & 3;
        int i = i0 + row;
        float m    = m_row[row];
        float ssum = ssum_row[row];
        float denom = fmaxf(fabsf(ssum), __expf(-m)) + 1e-6f;
        float inv = 1.f / denom;
        float o[16];
        #pragma unroll
        for (int k4 = 0; k4 < 4; k4++) {
            float4 v = *(const float4*)&Vs[row*AST + qd*16 + k4*4];
            o[k4*4+0] = v.x*inv; o[k4*4+1] = v.y*inv; o[k4*4+2] = v.z*inv; o[k4*4+3] = v.w*inv;
        }
        float mean = 0.f;
        #pragma unroll
        for (int d = 0; d < 16; d++) mean += o[d];
        mean += __shfl_xor_sync(0xffffffffu, mean, 1);
        mean += __shfl_xor_sync(0xffffffffu, mean, 2);
        mean *= (1.f / 64.f);
        float var = 0.f;
        #pragma unroll
        for (int d = 0; d < 16; d++) { float df = o[d] - mean; var += df * df; }
        var += __shfl_xor_sync(0xffffffffu, var, 1);
        var += __shfl_xor_sync(0xffffffffu, var, 2);
        var *= (1.f / 64.f);
        float rstd = rsqrtf(var + 1e-5f);
        size_t obase = ((size_t)(b*Sq + i)) * INNERq + h*DHq + qd*16;
        #pragma unroll
        for (int d = 0; d < 16; d++) {
            int c = h*DHq + qd*16 + d;
            float hn  = (o[d] - mean) * rstd * norm_w[c];
            float za  = g_z[obase + d];
            float sil = za / (1.f + __expf(-za));
            g_h[obase + d] = (hn + skipw[c] * g_xa[obase + d]) * sil;
        }
    }
}

// ---------------- launch ----------------
extern "C" void kernel_launch(void* const* d_in, const int* in_sizes, int n_in,
                              void* d_out, int out_size)
{
    const float* x      = (const float*)d_in[0];
    const float* W_up   = (const float*)d_in[1];
    const float* conv_w = (const float*)d_in[2];
    const float* conv_b = (const float*)d_in[3];
    const float* Wq     = (const float*)d_in[4];
    const float* Wk     = (const float*)d_in[5];
    const float* Wv     = (const float*)d_in[6];
    const float* W_i    = (const float*)d_in[7];
    const float* b_i    = (const float*)d_in[8];
    const float* W_f    = (const float*)d_in[9];
    const float* b_f    = (const float*)d_in[10];
    const float* norm_w = (const float*)d_in[11];
    const float* skipw  = (const float*)d_in[12];
    const float* W_down = (const float*)d_in[13];
    float* out = (float*)d_out;

    cudaFuncSetAttribute(attn_kernel,
                         cudaFuncAttributeMaxDynamicSharedMemorySize, ATT_SMEM_BYTES);
    cudaFuncSetAttribute(gemm_up,
                         cudaFuncAttributeMaxDynamicSharedMemorySize, UP_SMEM_BYTES);
    cudaFuncSetAttribute(gemm_down,
                         cudaFuncAttributeMaxDynamicSharedMemorySize, DN_SMEM_BYTES);

    gemm_up<<<dim3(8, 32), 256, UP_SMEM_BYTES>>>(x, W_up);
    fused_conv_qkv_gates<<<Bq*Sq, 128>>>(conv_w, conv_b, Wq, Wk, Wv, W_i, b_i, W_f, b_f);
    scan_kernel<<<Bq*NHq, 1024>>>();
    attn_kernel<<<1024, 128, ATT_SMEM_BYTES>>>(norm_w, skipw);
    gemm_down<<<dim3(4, 32), 256, DN_SMEM_BYTES>>>(W_down, out);
}